// round 11
// baseline (speedup 1.0000x reference)
#include <cuda_runtime.h>
#include <cstdint>

// RNN_50036368998466: B=1048576, T=3, H=32, D_IN=1.
// Stage 1 tabulated nearest-neighbor, TBL_N=8192 (err ~3.2e-5, 30x margin).
// Weights: Whh + W1p3 + wihb -> constant bank; W1p2 + W2 -> shared (port balance
// per R9/R10 evidence). Exact grid (no guards). Phase-3 dot chains split 2x for ILP.

typedef unsigned long long u64;

#define TBL_N    8192
#define TBL_LO   (-10.0f)
#define TBL_STEP (20.0f / 8191.0f)
#define TBL_INV  (8191.0f / 20.0f)
#define TBL_MAXF 8191.0f

__device__ __align__(16) float g_tbl[TBL_N * 48];
__device__ __align__(16) float g_wbuf[2432];
__constant__ __align__(16) float cbuf[1760];

// float offsets inside cbuf (16B aligned where float4-read)
#define OFF_WIHB 0      // float4[16]: (wih_2m, wih_2m+1, bsum_2m, bsum_2m+1)
#define OFF_WHH  64     // float[1024]: row-major W_hh[j][k]
#define OFF_W1P3 1088   // float2[256]: [(col-64)*8+q] = (W1[2q][col], W1[2q+1][col]), col 64..95
#define OFF_B2P  1600   // float2[4]
#define OFF_W3P  1608   // float2[4]
#define OFF_B3   1616
// g_wbuf extras destined for shared memory (copied per-CTA):
#define OFF_SMEM 1760   // start of smem image in g_wbuf
#define SM_W1P2  0      // float2[256]: [(col-32)*8+q], col 32..63  (floats 0..511)
#define SM_W2C   512    // float2[64]:  [k*4+m] = (W2[2m][k], W2[2m+1][k]) (floats 512..639)
#define SM_TOTAL 640

__device__ __forceinline__ u64 pk2(float lo, float hi) {
    u64 r; asm("mov.b64 %0, {%1,%2};" : "=l"(r) : "f"(lo), "f"(hi)); return r;
}
__device__ __forceinline__ float2 up2(u64 v) {
    float2 r; asm("mov.b64 {%0,%1}, %2;" : "=f"(r.x), "=f"(r.y) : "l"(v)); return r;
}
__device__ __forceinline__ u64 fma2(u64 a, u64 b, u64 c) {
    u64 d; asm("fma.rn.f32x2 %0, %1, %2, %3;" : "=l"(d) : "l"(a), "l"(b), "l"(c)); return d;
}
__device__ __forceinline__ void ld2wc(int fidx, u64& w0, u64& w1) {
    float4 v = *reinterpret_cast<const float4*>(&cbuf[fidx]);
    w0 = pk2(v.x, v.y);
    w1 = pk2(v.z, v.w);
}
__device__ __forceinline__ void ld2ws(const float* p, u64& w0, u64& w1) {
    float4 v = *reinterpret_cast<const float4*>(p);
    w0 = pk2(v.x, v.y);
    w1 = pk2(v.z, v.w);
}

// single-instruction tanh on the MUFU pipe (max abs err ~6e-4)
__device__ __forceinline__ float tanh_fast(float x) {
    float t; asm("tanh.approx.f32 %0, %1;" : "=f"(t) : "f"(x));
    return t;
}
__device__ __forceinline__ u64 relu2(u64 a) {
    float2 v = up2(a);
    return pk2(fmaxf(v.x, 0.0f), fmaxf(v.y, 0.0f));
}

// ---------------- table build + weight pack (block 0 also packs) ----------------
__global__ __launch_bounds__(128)
void build_table(const float* __restrict__ W_ih, const float* __restrict__ W_hh,
                 const float* __restrict__ b_ih, const float* __restrict__ b_hh,
                 const float* __restrict__ W1,   const float* __restrict__ b1,
                 const float* __restrict__ W2,   const float* __restrict__ b2,
                 const float* __restrict__ W3,   const float* __restrict__ b3) {
    __shared__ float sWih[32], sBsum[32], sWhh[1024], sW1a[512], sB1[16];
    const int tid = threadIdx.x;
    for (int i = tid; i < 1024; i += 128) sWhh[i] = W_hh[i];
    for (int i = tid; i < 512;  i += 128) { int r = i >> 5, c = i & 31; sW1a[i] = W1[r * 96 + c]; }
    if (tid < 32) { sWih[tid] = W_ih[tid]; sBsum[tid] = b_ih[tid] + b_hh[tid]; }
    if (tid < 16) sB1[tid] = b1[tid];
    __syncthreads();

    if (blockIdx.x == 0) {  // pack g_wbuf (constant image + smem image)
        if (tid < 16) {
            g_wbuf[OFF_WIHB + 4 * tid + 0] = sWih[2 * tid];
            g_wbuf[OFF_WIHB + 4 * tid + 1] = sWih[2 * tid + 1];
            g_wbuf[OFF_WIHB + 4 * tid + 2] = sBsum[2 * tid];
            g_wbuf[OFF_WIHB + 4 * tid + 3] = sBsum[2 * tid + 1];
        }
        for (int i = tid; i < 1024; i += 128)
            g_wbuf[OFF_WHH + i] = sWhh[i];
        for (int i = tid; i < 256; i += 128) {      // W1 cols 64..95 -> constant
            int col = 64 + (i >> 3), q = i & 7;
            g_wbuf[OFF_W1P3 + 2 * i + 0] = W1[(2 * q) * 96 + col];
            g_wbuf[OFF_W1P3 + 2 * i + 1] = W1[(2 * q + 1) * 96 + col];
        }
        for (int i = tid; i < 256; i += 128) {      // W1 cols 32..63 -> smem image
            int col = 32 + (i >> 3), q = i & 7;
            g_wbuf[OFF_SMEM + SM_W1P2 + 2 * i + 0] = W1[(2 * q) * 96 + col];
            g_wbuf[OFF_SMEM + SM_W1P2 + 2 * i + 1] = W1[(2 * q + 1) * 96 + col];
        }
        if (tid < 64) {                              // W2 -> smem image
            int k = tid >> 2, m = tid & 3;
            g_wbuf[OFF_SMEM + SM_W2C + 2 * tid + 0] = W2[(2 * m) * 16 + k];
            g_wbuf[OFF_SMEM + SM_W2C + 2 * tid + 1] = W2[(2 * m + 1) * 16 + k];
        }
        if (tid < 8) {
            g_wbuf[OFF_B2P + tid] = b2[tid];
            g_wbuf[OFF_W3P + tid] = W3[tid];
        }
        if (tid == 0) g_wbuf[OFF_B3] = b3[0];
    }

    const int idx = blockIdx.x * 128 + tid;
    if (idx >= TBL_N) return;
    const float x1 = TBL_LO + idx * TBL_STEP;

    float t[32], r[32];
#pragma unroll
    for (int j = 0; j < 32; j++) {
        t[j] = tanh_fast(fmaf(x1, sWih[j], sBsum[j]));
        r[j] = fmaxf(t[j], 0.0f);
    }
    for (int k = 0; k < 32; k++) {   // 4 partial sums break the latency chain
        float f0 = sBsum[k], f1 = 0.f, f2 = 0.f, f3 = 0.f;
#pragma unroll
        for (int j = 0; j < 32; j += 4) {
            f0 = fmaf(sWhh[k * 32 + j + 0], t[j + 0], f0);
            f1 = fmaf(sWhh[k * 32 + j + 1], t[j + 1], f1);
            f2 = fmaf(sWhh[k * 32 + j + 2], t[j + 2], f2);
            f3 = fmaf(sWhh[k * 32 + j + 3], t[j + 3], f3);
        }
        g_tbl[idx * 48 + k] = (f0 + f1) + (f2 + f3);
    }
    for (int i = 0; i < 16; i++) {
        float g0 = sB1[i], g1 = 0.f, g2 = 0.f, g3 = 0.f;
#pragma unroll
        for (int j = 0; j < 32; j += 4) {
            g0 = fmaf(sW1a[i * 32 + j + 0], r[j + 0], g0);
            g1 = fmaf(sW1a[i * 32 + j + 1], r[j + 1], g1);
            g2 = fmaf(sW1a[i * 32 + j + 2], r[j + 2], g2);
            g3 = fmaf(sW1a[i * 32 + j + 3], r[j + 3], g3);
        }
        g_tbl[idx * 48 + 32 + i] = (g0 + g1) + (g2 + g3);
    }
}

// ---------------- main kernel: 2 elems/thread; Whh+W1p3 in cbank, W1p2+W2 in smem ----------------
__global__ __launch_bounds__(128, 4)
void rnn_main(const float* __restrict__ x, float* __restrict__ out, int n_half) {
    __shared__ __align__(16) float sW[SM_TOTAL];   // [0..511]=W1p2, [512..639]=W2
    const int tid = threadIdx.x;
    const int gid = blockIdx.x * 128 + tid;        // grid divides exactly: no guards

    // ---- issue x load + table gather EARLY (latency overlaps smem preload) ----
    const float2* xp = reinterpret_cast<const float2*>(x) + (size_t)gid * 3;
    float2 v0 = xp[0], v1 = xp[1], v2 = xp[2];
    const float x1A = v0.x, x2A = v0.y, x3A = v1.x;
    const float x1B = v1.y, x2B = v2.x, x3B = v2.y;

    float ufA = fmaf(x1A - TBL_LO, TBL_INV, 0.5f);
    float ufB = fmaf(x1B - TBL_LO, TBL_INV, 0.5f);
    const int iA = (int)fminf(fmaxf(ufA, 0.0f), TBL_MAXF);
    const int iB = (int)fminf(fmaxf(ufB, 0.0f), TBL_MAXF);
    const float4* rA = reinterpret_cast<const float4*>(g_tbl + iA * 48);
    const float4* rB = reinterpret_cast<const float4*>(g_tbl + iB * 48);

    u64 accA[16], accB[16];  // pairs (k,k+1): step-2 preact, later h2
    u64 o1A[8],  o1B[8];     // pairs (i,i+1): fc1 accumulators
#pragma unroll
    for (int c = 0; c < 12; c++) {
        float4 vA = rA[c], vB = rB[c];
        if (c < 8) {
            accA[2*c] = pk2(vA.x, vA.y); accA[2*c+1] = pk2(vA.z, vA.w);
            accB[2*c] = pk2(vB.x, vB.y); accB[2*c+1] = pk2(vB.z, vB.w);
        } else {
            o1A[2*(c-8)] = pk2(vA.x, vA.y); o1A[2*(c-8)+1] = pk2(vA.z, vA.w);
            o1B[2*(c-8)] = pk2(vB.x, vB.y); o1B[2*(c-8)+1] = pk2(vB.z, vB.w);
        }
    }

    // ---- smem preload (overlapped with gather latency above) ----
    {
        const float4* src = reinterpret_cast<const float4*>(g_wbuf + OFF_SMEM);
        float4* dst = reinterpret_cast<float4*>(sW);
#pragma unroll
        for (int i = tid; i < SM_TOTAL / 4; i += 128) dst[i] = src[i];
    }
    __syncthreads();

    const u64 X2A = pk2(x2A, x2A), X2B = pk2(x2B, x2B);

    // ---- phase 2: h2 = tanh(acc + x2*wih) in place; o1 += relu(h2) x W1 cols 32..63 (smem) ----
#pragma unroll
    for (int p = 0; p < 16; p++) {
        const float4 wb = *reinterpret_cast<const float4*>(&cbuf[OFF_WIHB + 4 * p]);
        u64 W = pk2(wb.x, wb.y);
        float2 vA = up2(fma2(X2A, W, accA[p]));
        float2 vB = up2(fma2(X2B, W, accB[p]));
        float tA0 = tanh_fast(vA.x), tA1 = tanh_fast(vA.y);
        float tB0 = tanh_fast(vB.x), tB1 = tanh_fast(vB.y);
        accA[p] = pk2(tA0, tA1);
        accB[p] = pk2(tB0, tB1);
        u64 RA0 = pk2(fmaxf(tA0,0.f), fmaxf(tA0,0.f)), RA1 = pk2(fmaxf(tA1,0.f), fmaxf(tA1,0.f));
        u64 RB0 = pk2(fmaxf(tB0,0.f), fmaxf(tB0,0.f)), RB1 = pk2(fmaxf(tB1,0.f), fmaxf(tB1,0.f));
        const int c0 = 2 * p, c1 = 2 * p + 1;   // (col-32)
#pragma unroll
        for (int q = 0; q < 8; q += 2) {
            u64 wa0, wa1; ld2ws(&sW[SM_W1P2 + 2 * (c0 * 8 + q)], wa0, wa1);
            o1A[q]   = fma2(RA0, wa0, o1A[q]);   o1A[q+1] = fma2(RA0, wa1, o1A[q+1]);
            o1B[q]   = fma2(RB0, wa0, o1B[q]);   o1B[q+1] = fma2(RB0, wa1, o1B[q+1]);
            u64 wc0, wc1; ld2ws(&sW[SM_W1P2 + 2 * (c1 * 8 + q)], wc0, wc1);
            o1A[q]   = fma2(RA1, wc0, o1A[q]);   o1A[q+1] = fma2(RA1, wc1, o1A[q+1]);
            o1B[q]   = fma2(RB1, wc0, o1B[q]);   o1B[q+1] = fma2(RB1, wc1, o1B[q+1]);
        }
    }

    // ---- phase 3: h3_j = tanh(x3*wih_j + bsum_j + Whh[j]·h2) (cbank); o1 += relu x W1 cols 64..95 (cbank) ----
#pragma unroll 2
    for (int m = 0; m < 16; m++) {
        const int j0 = 2 * m, j1 = 2 * m + 1;
        // split chains: 8 accumulators, 8-deep each
        u64 dA0a = 0ull, dA0b = 0ull, dA1a = 0ull, dA1b = 0ull;
        u64 dB0a = 0ull, dB0b = 0ull, dB1a = 0ull, dB1b = 0ull;
#pragma unroll
        for (int p = 0; p < 16; p += 2) {
            u64 w0, w1; ld2wc(OFF_WHH + j0 * 32 + 2 * p, w0, w1);
            dA0a = fma2(accA[p], w0, dA0a); dA0b = fma2(accA[p+1], w1, dA0b);
            dB0a = fma2(accB[p], w0, dB0a); dB0b = fma2(accB[p+1], w1, dB0b);
            u64 u0, u1; ld2wc(OFF_WHH + j1 * 32 + 2 * p, u0, u1);
            dA1a = fma2(accA[p], u0, dA1a); dA1b = fma2(accA[p+1], u1, dA1b);
            dB1a = fma2(accB[p], u0, dB1a); dB1b = fma2(accB[p+1], u1, dB1b);
        }
        const float4 wb = *reinterpret_cast<const float4*>(&cbuf[OFF_WIHB + 4 * m]);
        float2 sA0 = up2(fma2(pk2(1.f,1.f), dA0a, dA0b));
        float2 sA1 = up2(fma2(pk2(1.f,1.f), dA1a, dA1b));
        float2 sB0 = up2(fma2(pk2(1.f,1.f), dB0a, dB0b));
        float2 sB1v = up2(fma2(pk2(1.f,1.f), dB1a, dB1b));
        float tA0 = tanh_fast(fmaf(x3A, wb.x, wb.z) + (sA0.x + sA0.y));
        float tA1 = tanh_fast(fmaf(x3A, wb.y, wb.w) + (sA1.x + sA1.y));
        float tB0 = tanh_fast(fmaf(x3B, wb.x, wb.z) + (sB0.x + sB0.y));
        float tB1 = tanh_fast(fmaf(x3B, wb.y, wb.w) + (sB1v.x + sB1v.y));
        u64 RA0 = pk2(fmaxf(tA0,0.f), fmaxf(tA0,0.f)), RA1 = pk2(fmaxf(tA1,0.f), fmaxf(tA1,0.f));
        u64 RB0 = pk2(fmaxf(tB0,0.f), fmaxf(tB0,0.f)), RB1 = pk2(fmaxf(tB1,0.f), fmaxf(tB1,0.f));
        const int c0 = j0, c1 = j1;   // (col-64) for cols 64..95
#pragma unroll
        for (int q = 0; q < 8; q += 2) {
            u64 wa0, wa1; ld2wc(OFF_W1P3 + 2 * (c0 * 8 + q), wa0, wa1);
            o1A[q]   = fma2(RA0, wa0, o1A[q]);   o1A[q+1] = fma2(RA0, wa1, o1A[q+1]);
            o1B[q]   = fma2(RB0, wa0, o1B[q]);   o1B[q+1] = fma2(RB0, wa1, o1B[q+1]);
            u64 wc0, wc1; ld2wc(OFF_W1P3 + 2 * (c1 * 8 + q), wc0, wc1);
            o1A[q]   = fma2(RA1, wc0, o1A[q]);   o1A[q+1] = fma2(RA1, wc1, o1A[q+1]);
            o1B[q]   = fma2(RB1, wc0, o1B[q]);   o1B[q+1] = fma2(RB1, wc1, o1B[q+1]);
        }
    }

    // ---- fc2 (weights in smem) ----
    u64 o2A[4], o2B[4];
#pragma unroll
    for (int m = 0; m < 4; m++) {
        const float2 b = *reinterpret_cast<const float2*>(&cbuf[OFF_B2P + 2 * m]);
        o2A[m] = pk2(b.x, b.y); o2B[m] = pk2(b.x, b.y);
    }
#pragma unroll
    for (int q = 0; q < 8; q++) {
        float2 vA = up2(o1A[q]), vB = up2(o1B[q]);
        u64 KaA = pk2(vA.x, vA.x), KbA = pk2(vA.y, vA.y);
        u64 KaB = pk2(vB.x, vB.x), KbB = pk2(vB.y, vB.y);
        const int k0 = 2 * q, k1 = 2 * q + 1;
        u64 w0, w1;
        ld2ws(&sW[SM_W2C + 2 * (k0 * 4 + 0)], w0, w1);
        o2A[0] = fma2(KaA, w0, o2A[0]); o2A[1] = fma2(KaA, w1, o2A[1]);
        o2B[0] = fma2(KaB, w0, o2B[0]); o2B[1] = fma2(KaB, w1, o2B[1]);
        ld2ws(&sW[SM_W2C + 2 * (k0 * 4 + 2)], w0, w1);
        o2A[2] = fma2(KaA, w0, o2A[2]); o2A[3] = fma2(KaA, w1, o2A[3]);
        o2B[2] = fma2(KaB, w0, o2B[2]); o2B[3] = fma2(KaB, w1, o2B[3]);
        ld2ws(&sW[SM_W2C + 2 * (k1 * 4 + 0)], w0, w1);
        o2A[0] = fma2(KbA, w0, o2A[0]); o2A[1] = fma2(KbA, w1, o2A[1]);
        o2B[0] = fma2(KbB, w0, o2B[0]); o2B[1] = fma2(KbB, w1, o2B[1]);
        ld2ws(&sW[SM_W2C + 2 * (k1 * 4 + 2)], w0, w1);
        o2A[2] = fma2(KbA, w0, o2A[2]); o2A[3] = fma2(KbA, w1, o2A[3]);
        o2B[2] = fma2(KbB, w0, o2B[2]); o2B[3] = fma2(KbB, w1, o2B[3]);
    }

    // ---- relu + fc3 ----
    u64 AA = 0ull, AB = 0ull;
#pragma unroll
    for (int m = 0; m < 4; m++) {
        const float2 w3 = *reinterpret_cast<const float2*>(&cbuf[OFF_W3P + 2 * m]);
        u64 w = pk2(w3.x, w3.y);
        AA = fma2(relu2(o2A[m]), w, AA);
        AB = fma2(relu2(o2B[m]), w, AB);
    }
    const float bias3 = cbuf[OFF_B3];
    float2 fa = up2(AA), fb = up2(AB);
    float2 res = make_float2(fa.x + fa.y + bias3, fb.x + fb.y + bias3);
    reinterpret_cast<float2*>(out)[gid] = res;
}

extern "C" void kernel_launch(void* const* d_in, const int* in_sizes, int n_in,
                              void* d_out, int out_size) {
    const float* x    = (const float*)d_in[0];
    const float* W_ih = (const float*)d_in[1];
    const float* W_hh = (const float*)d_in[2];
    const float* b_ih = (const float*)d_in[3];
    const float* b_hh = (const float*)d_in[4];
    const float* W1   = (const float*)d_in[5];
    const float* b1   = (const float*)d_in[6];
    const float* W2   = (const float*)d_in[7];
    const float* b2   = (const float*)d_in[8];
    const float* W3   = (const float*)d_in[9];
    const float* b3   = (const float*)d_in[10];
    float* out = (float*)d_out;

    const int B = in_sizes[0] / 3;   // x is [B, 3, 1]
    const int n_half = B / 2;        // 524288 = 4096 * 128 exactly

    build_table<<<TBL_N / 128, 128>>>(W_ih, W_hh, b_ih, b_hh, W1, b1, W2, b2, W3, b3);

    void* wbuf_dev = nullptr;
    cudaGetSymbolAddress(&wbuf_dev, g_wbuf);
    cudaMemcpyToSymbolAsync(cbuf, wbuf_dev, 1760 * sizeof(float), 0,
                            cudaMemcpyDeviceToDevice, 0);

    rnn_main<<<n_half / 128, 128>>>(x, out, n_half);
}

// round 13
// speedup vs baseline: 1.1185x; 1.1185x over previous
#include <cuda_runtime.h>
#include <cuda_bf16.h>
#include <cstdint>

// RNN_50036368998466 via warp-level HMMA (mma.sync m16n8k16 bf16 — baseline ISA,
// compiles for plain sm_103; tcgen05 is rejected by this build's PTX target).
// Warp = 32 batch rows (2 m-tiles). bf16-split 3-term GEMMs (K=96: A=[hi,lo,hi],
// B=[Whi,Whi,Wlo], residual ~1e-5). Chain stays in fragments: C(m16n8) frags map
// directly onto A(m16k16) k-tiles, so tanh/+bias/relu happen in registers.
// fc1 accumulates in C-frags across steps; smem transpose; scalar fc2/fc3.

typedef uint32_t u32;

__device__ __align__(16) float g_wbuf[240];
__constant__ __align__(16) float cbuf[240];
// cbuf: [0..31] wih, [32..63] bsum(=b_ih+b_hh), [64..79] b1, [80..207] W2,
//       [208..215] b2, [216..223] W3, [224] b3
// B images (bf16): [0,3072) Whh-B 32 rows x K96; [3072 + 1536*t) W1-B_t 16 rows x K96
__device__ __align__(16) __nv_bfloat16 g_bimg[7680];   // 15360 bytes

__device__ __forceinline__ float tanh_fast(float x) {
    float t; asm("tanh.approx.f32 %0, %1;" : "=f"(t) : "f"(x));
    return t;
}
__device__ __forceinline__ u32 pack_bf16(float a, float b) {  // lo=a, hi=b
    u32 r; asm("cvt.rn.bf16x2.f32 %0, %1, %2;" : "=r"(r) : "f"(b), "f"(a));
    return r;
}
// split 4 values -> hi pair-regs + lo(residue) pair-regs
__device__ __forceinline__ void split4(float v0, float v1, float v2, float v3,
                                       u32& h01, u32& h23, u32& l01, u32& l23) {
    h01 = pack_bf16(v0, v1); h23 = pack_bf16(v2, v3);
    float f0 = __uint_as_float(h01 << 16), f1 = __uint_as_float(h01 & 0xffff0000u);
    float f2 = __uint_as_float(h23 << 16), f3 = __uint_as_float(h23 & 0xffff0000u);
    l01 = pack_bf16(v0 - f0, v1 - f1); l23 = pack_bf16(v2 - f2, v3 - f3);
}
__device__ __forceinline__ u32 smem_u32(const void* p) {
    u32 a;
    asm("{ .reg .u64 t; cvta.to.shared.u64 t, %1; cvt.u32.u64 %0, t; }" : "=r"(a) : "l"(p));
    return a;
}
__device__ __forceinline__ void ldsm4(u32 a, u32& r0, u32& r1, u32& r2, u32& r3) {
    asm volatile("ldmatrix.sync.aligned.m8n8.x4.shared.b16 {%0,%1,%2,%3}, [%4];"
                 : "=r"(r0), "=r"(r1), "=r"(r2), "=r"(r3) : "r"(a));
}
__device__ __forceinline__ void mma16816(float* c, const u32* a, u32 b0, u32 b1) {
    asm volatile("mma.sync.aligned.m16n8k16.row.col.f32.bf16.bf16.f32 "
                 "{%0,%1,%2,%3}, {%4,%5,%6,%7}, {%8,%9}, {%0,%1,%2,%3};"
                 : "+f"(c[0]), "+f"(c[1]), "+f"(c[2]), "+f"(c[3])
                 : "r"(a[0]), "r"(a[1]), "r"(a[2]), "r"(a[3]), "r"(b0), "r"(b1));
}

// ---------------- pack kernel ----------------
__global__ __launch_bounds__(128)
void pack_weights(const float* __restrict__ W_ih, const float* __restrict__ W_hh,
                  const float* __restrict__ b_ih, const float* __restrict__ b_hh,
                  const float* __restrict__ W1,   const float* __restrict__ b1,
                  const float* __restrict__ W2,   const float* __restrict__ b2,
                  const float* __restrict__ W3,   const float* __restrict__ b3) {
    const int tid = threadIdx.x;
    if (tid < 32) { g_wbuf[tid] = W_ih[tid]; g_wbuf[32 + tid] = b_ih[tid] + b_hh[tid]; }
    if (tid < 16) g_wbuf[64 + tid] = b1[tid];
    g_wbuf[80 + tid] = W2[tid];
    if (tid < 8) { g_wbuf[208 + tid] = b2[tid]; g_wbuf[216 + tid] = W3[tid]; }
    if (tid == 0) g_wbuf[224] = b3[0];

    // Whh-B [n][k]: k<64 -> hi(Whh[n][k&31]); k>=64 -> lo
    for (int i = tid; i < 32 * 96; i += 128) {
        int n = i / 96, k = i % 96;
        float w = W_hh[n * 32 + (k & 31)];
        __nv_bfloat16 hi = __float2bfloat16(w);
        g_bimg[i] = (k < 64) ? hi : __float2bfloat16(w - __bfloat162float(hi));
    }
    // W1-B_t [n][k]: W1[n][32t + (k&31)], same hi/hi/lo
    for (int i = tid; i < 3 * 16 * 96; i += 128) {
        int t = i / 1536, r = i % 1536, n = r / 96, k = r % 96;
        float w = W1[n * 96 + 32 * t + (k & 31)];
        __nv_bfloat16 hi = __float2bfloat16(w);
        g_bimg[3072 + i] = (k < 64) ? hi : __float2bfloat16(w - __bfloat162float(hi));
    }
}

// ---------------- main kernel ----------------
__global__ __launch_bounds__(128, 3)
void rnn_hmma(const float* __restrict__ x, float* __restrict__ out) {
    __shared__ __align__(16) __nv_bfloat16 sB[7680];   // 15360 B
    __shared__ float sWih[32], sBsum[32];
    __shared__ float sX[3][128];
    __shared__ __align__(16) float sO1[128 * 20];

    const int tid = threadIdx.x;
    {   // stage B (960 float4)
        const float4* src = reinterpret_cast<const float4*>(g_bimg);
        float4* dst = reinterpret_cast<float4*>(sB);
#pragma unroll
        for (int i = 0; i < 8; i++) {
            int idx = tid + i * 128;
            if (idx < 960) dst[idx] = src[idx];
        }
    }
    if (tid < 32) { sWih[tid] = cbuf[tid]; sBsum[tid] = cbuf[32 + tid]; }
    {
        const float* xe = x + 3 * (size_t)(blockIdx.x * 128 + tid);
        sX[0][tid] = xe[0]; sX[1][tid] = xe[1]; sX[2][tid] = xe[2];
    }
    __syncthreads();

    const int lane = tid & 31, w = tid >> 5;
    const int g = lane >> 2, t = lane & 3;

    // per-lane column weights: wihc[2nt+p] = wih[8nt+2t+p]
    float wihc[8], bsc[8];
#pragma unroll
    for (int nt = 0; nt < 4; nt++) {
        wihc[2 * nt]     = sWih[8 * nt + 2 * t];
        wihc[2 * nt + 1] = sWih[8 * nt + 2 * t + 1];
        bsc[2 * nt]      = sBsum[8 * nt + 2 * t];
        bsc[2 * nt + 1]  = sBsum[8 * nt + 2 * t + 1];
    }
    // per-lane x values for rows {g, g+8, g+16, g+24} of this warp's 32 rows
    const int rr = 32 * w + g;
    float xr[3][4];
#pragma unroll
    for (int s = 0; s < 3; s++) {
        xr[s][0] = sX[s][rr];      xr[s][1] = sX[s][rr + 8];
        xr[s][2] = sX[s][rr + 16]; xr[s][3] = sX[s][rr + 24];
    }

    const u32 sBaddr = smem_u32(sB);
    // ldmatrix x4 lane address offset: matrices (ntA,klo),(ntA,khi),(ntB,klo),(ntB,khi)
    const u32 boff = (u32)((((lane >> 4) & 1) * 8 + (lane & 7)) * 192 + ((lane >> 3) & 1) * 16);

    u32 Ah[2][8], Al[2][8];      // A frags per m-tile: regs [kt01*4 + half*2 + j]
    float O1[2][2][4];           // fc1 C frags (persistent)
    float Cr[2][4][4];           // recurrence C frags
#pragma unroll
    for (int a = 0; a < 2; a++)
#pragma unroll
        for (int b = 0; b < 2; b++)
#pragma unroll
            for (int c = 0; c < 4; c++) O1[a][b][c] = 0.f;

    // ---- step 1: h1 = tanh(x1*wih + bsum) directly in fragment positions ----
#pragma unroll
    for (int mt = 0; mt < 2; mt++) {
        float xq0 = xr[0][2 * mt], xq1 = xr[0][2 * mt + 1];
#pragma unroll
        for (int nt = 0; nt < 4; nt++) {
            float v0 = tanh_fast(fmaf(xq0, wihc[2 * nt],     bsc[2 * nt]));
            float v1 = tanh_fast(fmaf(xq0, wihc[2 * nt + 1], bsc[2 * nt + 1]));
            float v2 = tanh_fast(fmaf(xq1, wihc[2 * nt],     bsc[2 * nt]));
            float v3 = tanh_fast(fmaf(xq1, wihc[2 * nt + 1], bsc[2 * nt + 1]));
            int base = (nt >> 1) * 4 + (nt & 1) * 2;
            split4(v0, v1, v2, v3, Ah[mt][base], Ah[mt][base + 1], Al[mt][base], Al[mt][base + 1]);
        }
    }

#define REC_GEMM() do { \
    _Pragma("unroll") \
    for (int mt = 0; mt < 2; mt++) \
        _Pragma("unroll") \
        for (int nt = 0; nt < 4; nt++) \
            _Pragma("unroll") \
            for (int j = 0; j < 4; j++) Cr[mt][nt][j] = 0.f; \
    _Pragma("unroll") \
    for (int kt = 0; kt < 6; kt++) { \
        _Pragma("unroll") \
        for (int pair = 0; pair < 2; pair++) { \
            u32 b0, b1, b2, b3; \
            ldsm4(sBaddr + (u32)(pair * 3072 + kt * 32) + boff, b0, b1, b2, b3); \
            _Pragma("unroll") \
            for (int mt = 0; mt < 2; mt++) { \
                const u32* A = (kt >= 2 && kt < 4) ? &Al[mt][(kt & 1) * 4] : &Ah[mt][(kt & 1) * 4]; \
                mma16816(Cr[mt][2 * pair],     A, b0, b1); \
                mma16816(Cr[mt][2 * pair + 1], A, b2, b3); \
            } \
        } \
    } \
} while (0)

#define RELU_A() do { \
    _Pragma("unroll") \
    for (int mt = 0; mt < 2; mt++) \
        _Pragma("unroll") \
        for (int i = 0; i < 8; i++) { \
            u32 s = Ah[mt][i]; \
            u32 m = ((s >> 15) & 0x10001u) * 0xffffu; \
            Ah[mt][i] = s & ~m; \
            Al[mt][i] = Al[mt][i] & ~m; \
        } \
} while (0)

#define FC1_GEMM(step) do { \
    _Pragma("unroll") \
    for (int kt = 0; kt < 6; kt++) { \
        u32 b0, b1, b2, b3; \
        ldsm4(sBaddr + (u32)(6144 + 3072 * (step) + kt * 32) + boff, b0, b1, b2, b3); \
        _Pragma("unroll") \
        for (int mt = 0; mt < 2; mt++) { \
            const u32* A = (kt >= 2 && kt < 4) ? &Al[mt][(kt & 1) * 4] : &Ah[mt][(kt & 1) * 4]; \
            mma16816(O1[mt][0], A, b0, b1); \
            mma16816(O1[mt][1], A, b2, b3); \
        } \
    } \
} while (0)

// conversion: Cr + x_s -> tanh -> A frags (s = 1 for x2, 2 for x3)
#define CONV(sidx) do { \
    _Pragma("unroll") \
    for (int mt = 0; mt < 2; mt++) { \
        float xq0 = xr[sidx][2 * mt], xq1 = xr[sidx][2 * mt + 1]; \
        _Pragma("unroll") \
        for (int nt = 0; nt < 4; nt++) { \
            float v0 = tanh_fast(Cr[mt][nt][0] + fmaf(xq0, wihc[2 * nt],     bsc[2 * nt])); \
            float v1 = tanh_fast(Cr[mt][nt][1] + fmaf(xq0, wihc[2 * nt + 1], bsc[2 * nt + 1])); \
            float v2 = tanh_fast(Cr[mt][nt][2] + fmaf(xq1, wihc[2 * nt],     bsc[2 * nt])); \
            float v3 = tanh_fast(Cr[mt][nt][3] + fmaf(xq1, wihc[2 * nt + 1], bsc[2 * nt + 1])); \
            int base = (nt >> 1) * 4 + (nt & 1) * 2; \
            split4(v0, v1, v2, v3, Ah[mt][base], Ah[mt][base + 1], Al[mt][base], Al[mt][base + 1]); \
        } \
    } \
} while (0)

    // step 1: recurrence (h1 -> pre2), then fc1(relu(h1), W1 block 0)
    REC_GEMM();
    RELU_A();
    FC1_GEMM(0);

    // step 2: h2 = tanh(pre2 + x2 terms); recurrence -> pre3; fc1 block 1
    CONV(1);
    REC_GEMM();
    RELU_A();
    FC1_GEMM(1);

    // step 3: h3 = tanh(pre3 + x3 terms); relu applied directly before split
#pragma unroll
    for (int mt = 0; mt < 2; mt++) {
        float xq0 = xr[2][2 * mt], xq1 = xr[2][2 * mt + 1];
#pragma unroll
        for (int nt = 0; nt < 4; nt++) {
            float v0 = fmaxf(tanh_fast(Cr[mt][nt][0] + fmaf(xq0, wihc[2 * nt],     bsc[2 * nt])), 0.f);
            float v1 = fmaxf(tanh_fast(Cr[mt][nt][1] + fmaf(xq0, wihc[2 * nt + 1], bsc[2 * nt + 1])), 0.f);
            float v2 = fmaxf(tanh_fast(Cr[mt][nt][2] + fmaf(xq1, wihc[2 * nt],     bsc[2 * nt])), 0.f);
            float v3 = fmaxf(tanh_fast(Cr[mt][nt][3] + fmaf(xq1, wihc[2 * nt + 1], bsc[2 * nt + 1])), 0.f);
            int base = (nt >> 1) * 4 + (nt & 1) * 2;
            split4(v0, v1, v2, v3, Ah[mt][base], Ah[mt][base + 1], Al[mt][base], Al[mt][base + 1]);
        }
    }
    FC1_GEMM(2);

    // ---- epilogue: transpose o1 frags through smem, scalar fc2/fc3 ----
#pragma unroll
    for (int mt = 0; mt < 2; mt++) {
        int lr = 32 * w + 16 * mt + g;
#pragma unroll
        for (int nt = 0; nt < 2; nt++) {
            int c = 8 * nt + 2 * t;
            *reinterpret_cast<float2*>(&sO1[lr * 20 + c]) =
                make_float2(O1[mt][nt][0], O1[mt][nt][1]);
            *reinterpret_cast<float2*>(&sO1[(lr + 8) * 20 + c]) =
                make_float2(O1[mt][nt][2], O1[mt][nt][3]);
        }
    }
    __syncwarp();

    float o1f[16];
#pragma unroll
    for (int i = 0; i < 4; i++) {
        float4 v = *reinterpret_cast<const float4*>(&sO1[tid * 20 + 4 * i]);
        o1f[4 * i] = v.x; o1f[4 * i + 1] = v.y; o1f[4 * i + 2] = v.z; o1f[4 * i + 3] = v.w;
    }
#pragma unroll
    for (int i = 0; i < 16; i++) o1f[i] += cbuf[64 + i];

    float acc = cbuf[224];
#pragma unroll
    for (int i = 0; i < 8; i++) {
        float s = cbuf[208 + i];
#pragma unroll
        for (int k = 0; k < 16; k++)
            s = fmaf(o1f[k], cbuf[80 + i * 16 + k], s);
        acc = fmaf(fmaxf(s, 0.0f), cbuf[216 + i], acc);
    }
    out[blockIdx.x * 128 + tid] = acc;
}

extern "C" void kernel_launch(void* const* d_in, const int* in_sizes, int n_in,
                              void* d_out, int out_size) {
    const float* x    = (const float*)d_in[0];
    const float* W_ih = (const float*)d_in[1];
    const float* W_hh = (const float*)d_in[2];
    const float* b_ih = (const float*)d_in[3];
    const float* b_hh = (const float*)d_in[4];
    const float* W1   = (const float*)d_in[5];
    const float* b1   = (const float*)d_in[6];
    const float* W2   = (const float*)d_in[7];
    const float* b2   = (const float*)d_in[8];
    const float* W3   = (const float*)d_in[9];
    const float* b3   = (const float*)d_in[10];
    float* out = (float*)d_out;

    const int B = in_sizes[0] / 3;   // 1048576 = 8192 * 128 exactly

    pack_weights<<<1, 128>>>(W_ih, W_hh, b_ih, b_hh, W1, b1, W2, b2, W3, b3);

    void* wbuf_dev = nullptr;
    cudaGetSymbolAddress(&wbuf_dev, g_wbuf);
    cudaMemcpyToSymbolAsync(cbuf, wbuf_dev, 240 * sizeof(float), 0,
                            cudaMemcpyDeviceToDevice, 0);

    rnn_hmma<<<B / 128, 128>>>(x, out);
}